// round 2
// baseline (speedup 1.0000x reference)
#include <cuda_runtime.h>
#include <cstdint>
#include <cstddef>

#define Bb 4
#define Nn 2048
#define Cc 1024
#define Hh 16
#define Dd 64

// Scratch (allocation-free rule: __device__ globals)
__device__ float g_qkv[(size_t)Bb * Nn * 3 * Cc];   // (B,N,3C)
__device__ float g_attn[(size_t)Bb * Nn * Cc];      // (B,N,C)

// ---------------------------------------------------------------------------
// helpers
// ---------------------------------------------------------------------------
__device__ __forceinline__ uint32_t f2tf(float x) {
    uint32_t r;
    asm("cvt.rna.tf32.f32 %0, %1;" : "=r"(r) : "f"(x));
    return r;
}

// 3xTF32 split: hi = tf32(x), lo = tf32(x - hi)
__device__ __forceinline__ void tfsplit(float x, uint32_t& hi, uint32_t& lo) {
    hi = f2tf(x);
    lo = f2tf(x - __uint_as_float(hi));
}

__device__ __forceinline__ void mma8(float* c, const uint32_t* a, uint32_t b0, uint32_t b1) {
    asm volatile(
        "mma.sync.aligned.m16n8k8.row.col.f32.tf32.tf32.f32 "
        "{%0,%1,%2,%3},{%4,%5,%6,%7},{%8,%9},{%0,%1,%2,%3};"
        : "+f"(c[0]), "+f"(c[1]), "+f"(c[2]), "+f"(c[3])
        : "r"(a[0]), "r"(a[1]), "r"(a[2]), "r"(a[3]), "r"(b0), "r"(b1));
}

// error-compensated 3-pass mma: c += al*bh + ah*bl + ah*bh
__device__ __forceinline__ void mma3(float* c,
                                     const uint32_t* ah, const uint32_t* al,
                                     uint32_t bh0, uint32_t bh1,
                                     uint32_t bl0, uint32_t bl1) {
    mma8(c, al, bh0, bh1);
    mma8(c, ah, bl0, bl1);
    mma8(c, ah, bh0, bh1);
}

__device__ __forceinline__ uint32_t sptr(const void* p) {
    return (uint32_t)__cvta_generic_to_shared(p);
}

#define CP16(dst, src) \
    asm volatile("cp.async.cg.shared.global [%0], [%1], 16;" :: "r"(sptr(dst)), "l"(src))
#define CP_COMMIT() asm volatile("cp.async.commit_group;" ::: "memory")
#define CP_WAIT1()  asm volatile("cp.async.wait_group 1;" ::: "memory")
#define CP_WAIT0()  asm volatile("cp.async.wait_group 0;" ::: "memory")

// ---------------------------------------------------------------------------
// GEMM: C[M,N] = A[M,K] @ B[K,N] + bias[N]   (row-major fp32, 3xTF32 mma)
// Block tile 128x128, K-tile 32, 256 threads, 8 warps each 32x64.
// ---------------------------------------------------------------------------
constexpr int BM = 128, BN = 128, BK = 32;
constexpr int PA = 36;    // A smem pitch: conflict-free A frags
constexpr int PB = 136;   // B smem pitch: conflict-free B frags
constexpr int ASZ = BM * PA;
constexpr int BSZ = BK * PB;
constexpr size_t GEMM_SMEM = (size_t)(ASZ + BSZ) * 2 * sizeof(float);

__global__ __launch_bounds__(256) void gemm_bias_tf32(
    const float* __restrict__ A, const float* __restrict__ Bm,
    const float* __restrict__ bias, float* __restrict__ Cm,
    int M, int N, int K)
{
    extern __shared__ float sm[];
    float* As = sm;                 // [2][ASZ]
    float* Bs = sm + 2 * ASZ;       // [2][BSZ]

    const int tid = threadIdx.x;
    const int m0 = blockIdx.y * BM;
    const int n0 = blockIdx.x * BN;

    const int warp = tid >> 5;
    const int lane = tid & 31;
    const int g = lane >> 2;        // 0..7
    const int t = lane & 3;         // 0..3
    const int warp_m = warp >> 1;   // 0..3  (32 rows each)
    const int warp_n = warp & 1;    // 0..1  (64 cols each)

    float acc[2][8][4] = {};

    const int KT = K / BK;

    auto load_stage = [&](int s, int kt) {
        const int k0 = kt * BK;
        #pragma unroll
        for (int i = 0; i < 4; i++) {
            int idx = i * 256 + tid;           // 1024 float4 of A tile
            int r = idx >> 3, c4 = (idx & 7) * 4;
            CP16(&As[s * ASZ + r * PA + c4], &A[(size_t)(m0 + r) * K + k0 + c4]);
        }
        #pragma unroll
        for (int i = 0; i < 4; i++) {
            int idx = i * 256 + tid;           // 1024 float4 of B tile
            int r = idx >> 5, c4 = (idx & 31) * 4;
            CP16(&Bs[s * BSZ + r * PB + c4], &Bm[(size_t)(k0 + r) * N + n0 + c4]);
        }
    };

    load_stage(0, 0);
    CP_COMMIT();

    for (int kt = 0; kt < KT; kt++) {
        if (kt + 1 < KT) {
            load_stage((kt + 1) & 1, kt + 1);
            CP_COMMIT();
            CP_WAIT1();
        } else {
            CP_WAIT0();
        }
        __syncthreads();

        const float* as = &As[(kt & 1) * ASZ];
        const float* bs = &Bs[(kt & 1) * BSZ];

        #pragma unroll
        for (int ks = 0; ks < 4; ks++) {
            uint32_t afh[2][4], afl[2][4];
            #pragma unroll
            for (int mt = 0; mt < 2; mt++) {
                int r = warp_m * 32 + mt * 16;
                tfsplit(as[(r + g) * PA + ks * 8 + t],        afh[mt][0], afl[mt][0]);
                tfsplit(as[(r + 8 + g) * PA + ks * 8 + t],    afh[mt][1], afl[mt][1]);
                tfsplit(as[(r + g) * PA + ks * 8 + t + 4],    afh[mt][2], afl[mt][2]);
                tfsplit(as[(r + 8 + g) * PA + ks * 8 + t + 4],afh[mt][3], afl[mt][3]);
            }
            #pragma unroll
            for (int nt = 0; nt < 8; nt++) {
                int cb = warp_n * 64 + nt * 8;
                uint32_t bh0, bl0, bh1, bl1;
                tfsplit(bs[(ks * 8 + t) * PB + cb + g],     bh0, bl0);
                tfsplit(bs[(ks * 8 + t + 4) * PB + cb + g], bh1, bl1);
                mma3(acc[0][nt], afh[0], afl[0], bh0, bh1, bl0, bl1);
                mma3(acc[1][nt], afh[1], afl[1], bh0, bh1, bl0, bl1);
            }
        }
        __syncthreads();
    }

    // epilogue: + bias, fp32 out
    #pragma unroll
    for (int mt = 0; mt < 2; mt++) {
        int r0 = m0 + warp_m * 32 + mt * 16 + g;
        #pragma unroll
        for (int nt = 0; nt < 8; nt++) {
            int c = n0 + warp_n * 64 + nt * 8 + 2 * t;
            float bz0 = bias[c], bz1 = bias[c + 1];
            float2 v0 = make_float2(acc[mt][nt][0] + bz0, acc[mt][nt][1] + bz1);
            float2 v1 = make_float2(acc[mt][nt][2] + bz0, acc[mt][nt][3] + bz1);
            *(float2*)&Cm[(size_t)r0 * N + c] = v0;
            *(float2*)&Cm[(size_t)(r0 + 8) * N + c] = v1;
        }
    }
}

// ---------------------------------------------------------------------------
// Flash attention (no sqrt(d) scaling, matching reference). 3xTF32 mma.
// Grid: (B*H, N/128). Block 256 threads = 8 warps, warp owns 16 query rows.
// ---------------------------------------------------------------------------
constexpr int PQ = 68;
constexpr int PK = 68;
constexpr int PV = 72;
constexpr int PP = 68;
constexpr int QSZ = 128 * PQ;
constexpr int KSZ = 64 * PK;
constexpr int VSZ = 64 * PV;
constexpr int PSZ = 128 * PP;
constexpr size_t FL_SMEM = (size_t)(QSZ + KSZ + VSZ + PSZ) * sizeof(float);

__global__ __launch_bounds__(256) void flash_attn(
    const float* __restrict__ qkv, float* __restrict__ attn_out)
{
    extern __shared__ float sm[];
    float* Qs = sm;
    float* Ks = Qs + QSZ;
    float* Vs = Ks + KSZ;
    float* Ps = Vs + VSZ;

    const int tid = threadIdx.x;
    const int bh = blockIdx.x;
    const int b = bh / Hh, h = bh % Hh;
    const int q0 = blockIdx.y * 128;

    const int warp = tid >> 5;
    const int lane = tid & 31;
    const int g = lane >> 2;
    const int t = lane & 3;

    const size_t row_stride = (size_t)3 * Cc;
    const size_t base = (size_t)(b * Nn) * row_stride;
    const int qoff = h * Dd;
    const int koff = Cc + h * Dd;
    const int voff = 2 * Cc + h * Dd;

    // load Q tile (128 x 64)
    #pragma unroll
    for (int i = 0; i < 8; i++) {
        int idx = i * 256 + tid;               // 2048 float4
        int r = idx >> 4, c4 = (idx & 15) * 4;
        float4 v = *(const float4*)&qkv[base + (size_t)(q0 + r) * row_stride + qoff + c4];
        *(float4*)&Qs[r * PQ + c4] = v;
    }

    float m_run[2] = { -1e30f, -1e30f };
    float l_run[2] = { 0.f, 0.f };
    float oacc[8][4] = {};

    const int rq = warp * 16;

    for (int kt = 0; kt < Nn / 64; kt++) {
        const int k0 = kt * 64;
        __syncthreads();

        // load K,V tiles (64 x 64 each)
        #pragma unroll
        for (int i = 0; i < 4; i++) {
            int idx = i * 256 + tid;           // 1024 float4
            int r = idx >> 4, c4 = (idx & 15) * 4;
            float4 kv = *(const float4*)&qkv[base + (size_t)(k0 + r) * row_stride + koff + c4];
            *(float4*)&Ks[r * PK + c4] = kv;
            float4 vv = *(const float4*)&qkv[base + (size_t)(k0 + r) * row_stride + voff + c4];
            *(float4*)&Vs[r * PV + c4] = vv;
        }
        __syncthreads();

        // S = Q K^T  (16 x 64 per warp), 3xTF32
        float s[8][4] = {};
        #pragma unroll
        for (int ks = 0; ks < 8; ks++) {
            uint32_t ah[4], al[4];
            tfsplit(Qs[(rq + g) * PQ + ks * 8 + t],         ah[0], al[0]);
            tfsplit(Qs[(rq + 8 + g) * PQ + ks * 8 + t],     ah[1], al[1]);
            tfsplit(Qs[(rq + g) * PQ + ks * 8 + t + 4],     ah[2], al[2]);
            tfsplit(Qs[(rq + 8 + g) * PQ + ks * 8 + t + 4], ah[3], al[3]);
            #pragma unroll
            for (int nt = 0; nt < 8; nt++) {
                uint32_t bh0, bl0, bh1, bl1;
                tfsplit(Ks[(nt * 8 + g) * PK + ks * 8 + t],     bh0, bl0);
                tfsplit(Ks[(nt * 8 + g) * PK + ks * 8 + t + 4], bh1, bl1);
                mma3(s[nt], ah, al, bh0, bh1, bl0, bl1);
            }
        }

        // online softmax per row (2 rows per thread: g, g+8)
        #pragma unroll
        for (int rr = 0; rr < 2; rr++) {
            int j0 = rr * 2;
            float mx = -1e30f;
            #pragma unroll
            for (int nt = 0; nt < 8; nt++)
                mx = fmaxf(mx, fmaxf(s[nt][j0], s[nt][j0 + 1]));
            mx = fmaxf(mx, __shfl_xor_sync(0xffffffffu, mx, 1));
            mx = fmaxf(mx, __shfl_xor_sync(0xffffffffu, mx, 2));
            float newm = fmaxf(m_run[rr], mx);
            float scale = __expf(m_run[rr] - newm);
            m_run[rr] = newm;
            float rsum = 0.f;
            #pragma unroll
            for (int nt = 0; nt < 8; nt++) {
                float p0 = __expf(s[nt][j0] - newm);
                float p1 = __expf(s[nt][j0 + 1] - newm);
                s[nt][j0] = p0; s[nt][j0 + 1] = p1;
                rsum += p0 + p1;
            }
            rsum += __shfl_xor_sync(0xffffffffu, rsum, 1);
            rsum += __shfl_xor_sync(0xffffffffu, rsum, 2);
            l_run[rr] = l_run[rr] * scale + rsum;
            #pragma unroll
            for (int nt = 0; nt < 8; nt++) {
                oacc[nt][j0] *= scale;
                oacc[nt][j0 + 1] *= scale;
            }
        }

        // P -> smem (per-warp private region)
        #pragma unroll
        for (int nt = 0; nt < 8; nt++) {
            Ps[(rq + g) * PP + nt * 8 + 2 * t] = s[nt][0];
            Ps[(rq + g) * PP + nt * 8 + 2 * t + 1] = s[nt][1];
            Ps[(rq + 8 + g) * PP + nt * 8 + 2 * t] = s[nt][2];
            Ps[(rq + 8 + g) * PP + nt * 8 + 2 * t + 1] = s[nt][3];
        }
        __syncwarp();

        // O += P V   (k = key dim 64), 3xTF32
        #pragma unroll
        for (int ks = 0; ks < 8; ks++) {
            uint32_t ah[4], al[4];
            tfsplit(Ps[(rq + g) * PP + ks * 8 + t],         ah[0], al[0]);
            tfsplit(Ps[(rq + 8 + g) * PP + ks * 8 + t],     ah[1], al[1]);
            tfsplit(Ps[(rq + g) * PP + ks * 8 + t + 4],     ah[2], al[2]);
            tfsplit(Ps[(rq + 8 + g) * PP + ks * 8 + t + 4], ah[3], al[3]);
            #pragma unroll
            for (int nt = 0; nt < 8; nt++) {
                uint32_t bh0, bl0, bh1, bl1;
                tfsplit(Vs[(ks * 8 + t) * PV + nt * 8 + g],     bh0, bl0);
                tfsplit(Vs[(ks * 8 + t + 4) * PV + nt * 8 + g], bh1, bl1);
                mma3(oacc[nt], ah, al, bh0, bh1, bl0, bl1);
            }
        }
    }

    // normalize + write out: attn_out[(b*N + n) * C + h*D + d]
    float inv0 = 1.f / l_run[0];
    float inv1 = 1.f / l_run[1];
    size_t orow0 = (size_t)(b * Nn + q0 + rq + g) * Cc + h * Dd;
    size_t orow1 = (size_t)(b * Nn + q0 + rq + 8 + g) * Cc + h * Dd;
    #pragma unroll
    for (int nt = 0; nt < 8; nt++) {
        int c = nt * 8 + 2 * t;
        *(float2*)&attn_out[orow0 + c] = make_float2(oacc[nt][0] * inv0, oacc[nt][1] * inv0);
        *(float2*)&attn_out[orow1 + c] = make_float2(oacc[nt][2] * inv1, oacc[nt][3] * inv1);
    }
}

// ---------------------------------------------------------------------------
// launch
// ---------------------------------------------------------------------------
extern "C" void kernel_launch(void* const* d_in, const int* in_sizes, int n_in,
                              void* d_out, int out_size)
{
    const float* x     = (const float*)d_in[0];
    const float* w_in  = (const float*)d_in[1];
    const float* b_in  = (const float*)d_in[2];
    const float* w_out = (const float*)d_in[3];
    const float* b_out = (const float*)d_in[4];
    float* out = (float*)d_out;

    float* qkv;
    float* attn;
    cudaGetSymbolAddress((void**)&qkv, g_qkv);
    cudaGetSymbolAddress((void**)&attn, g_attn);

    cudaFuncSetAttribute(gemm_bias_tf32, cudaFuncAttributeMaxDynamicSharedMemorySize,
                         (int)GEMM_SMEM);
    cudaFuncSetAttribute(flash_attn, cudaFuncAttributeMaxDynamicSharedMemorySize,
                         (int)FL_SMEM);

    const int M = Bb * Nn;  // 8192

    // 1) qkv = x @ w_in + b_in     (8192 x 3072 x 1024)
    gemm_bias_tf32<<<dim3(3 * Cc / BN, M / BM), 256, GEMM_SMEM>>>(
        x, w_in, b_in, qkv, M, 3 * Cc, Cc);

    // 2) flash attention -> attn (B,N,C)
    flash_attn<<<dim3(Bb * Hh, Nn / 128), 256, FL_SMEM>>>(qkv, attn);

    // 3) out = attn @ w_out + b_out   (8192 x 1024 x 1024)
    gemm_bias_tf32<<<dim3(Cc / BN, M / BM), 256, GEMM_SMEM>>>(
        attn, w_out, b_out, out, M, Cc, Cc);
}

// round 3
// speedup vs baseline: 1.5925x; 1.5925x over previous
#include <cuda_runtime.h>
#include <cuda_bf16.h>
#include <cstdint>
#include <cstddef>

#define Bb 4
#define Nn 2048
#define Cc 1024
#define Hh 16
#define Dd 64

// Scratch (allocation-free rule: __device__ globals)
__device__ float g_qkv[(size_t)Bb * Nn * 3 * Cc];   // (B,N,3C)
__device__ float g_attn[(size_t)Bb * Nn * Cc];      // (B,N,C)

// ---------------------------------------------------------------------------
// helpers
// ---------------------------------------------------------------------------
// bf16x3 split of a pair: h = packed bf16x2 of hi parts (lo half = x0),
// l = packed bf16x2 of residuals.
__device__ __forceinline__ void bsplit2(float x0, float x1, uint32_t& h, uint32_t& l) {
    __nv_bfloat162 hv = __floats2bfloat162_rn(x0, x1);
    float2 hf = __bfloat1622float2(hv);
    __nv_bfloat162 lv = __floats2bfloat162_rn(x0 - hf.x, x1 - hf.y);
    h = *reinterpret_cast<uint32_t*>(&hv);
    l = *reinterpret_cast<uint32_t*>(&lv);
}

__device__ __forceinline__ uint32_t bpack2(float x0, float x1) {
    __nv_bfloat162 hv = __floats2bfloat162_rn(x0, x1);
    return *reinterpret_cast<uint32_t*>(&hv);
}

// m16n8k16 bf16 mma, fp32 accumulate
__device__ __forceinline__ void mmabf(float* c, const uint32_t* a, uint32_t b0, uint32_t b1) {
    asm volatile(
        "mma.sync.aligned.m16n8k16.row.col.f32.bf16.bf16.f32 "
        "{%0,%1,%2,%3},{%4,%5,%6,%7},{%8,%9},{%0,%1,%2,%3};"
        : "+f"(c[0]), "+f"(c[1]), "+f"(c[2]), "+f"(c[3])
        : "r"(a[0]), "r"(a[1]), "r"(a[2]), "r"(a[3]), "r"(b0), "r"(b1));
}

// error-compensated: c += al*bh + ah*bl + ah*bh
__device__ __forceinline__ void mma3(float* c,
                                     const uint32_t* ah, const uint32_t* al,
                                     uint32_t bh0, uint32_t bh1,
                                     uint32_t bl0, uint32_t bl1) {
    mmabf(c, al, bh0, bh1);
    mmabf(c, ah, bl0, bl1);
    mmabf(c, ah, bh0, bh1);
}

__device__ __forceinline__ uint32_t sptr(const void* p) {
    return (uint32_t)__cvta_generic_to_shared(p);
}

#define CP16(dst, src) \
    asm volatile("cp.async.cg.shared.global [%0], [%1], 16;" :: "r"(sptr(dst)), "l"(src))
#define CP_COMMIT() asm volatile("cp.async.commit_group;" ::: "memory")
#define CP_WAIT1()  asm volatile("cp.async.wait_group 1;" ::: "memory")
#define CP_WAIT0()  asm volatile("cp.async.wait_group 0;" ::: "memory")

// ---------------------------------------------------------------------------
// GEMM: C[M,N] = A[M,K] @ B[K,N] + bias[N]   (row-major fp32, bf16x3 mma)
// Block tile 128x128, K-tile 32, 256 threads, 8 warps each 32x64.
// ---------------------------------------------------------------------------
constexpr int BM = 128, BN = 128, BK = 32;
constexpr int PA = 40;    // fp32 A pitch: (8g+2t) per LDS.64 half-phase conflict-free
constexpr int PB = 132;   // fp32 B pitch: 2*PB mod 32banks == 8 -> (8t+g) conflict-free
constexpr int ASZ = BM * PA;
constexpr int BSZ = BK * PB;
constexpr size_t GEMM_SMEM = (size_t)(ASZ + BSZ) * 2 * sizeof(float);

__global__ __launch_bounds__(256) void gemm_bias_bf16x3(
    const float* __restrict__ A, const float* __restrict__ Bm,
    const float* __restrict__ bias, float* __restrict__ Cm,
    int M, int N, int K)
{
    extern __shared__ float sm[];
    float* As = sm;                 // [2][ASZ]
    float* Bs = sm + 2 * ASZ;       // [2][BSZ]

    const int tid = threadIdx.x;
    const int m0 = blockIdx.y * BM;
    const int n0 = blockIdx.x * BN;

    const int warp = tid >> 5;
    const int lane = tid & 31;
    const int g = lane >> 2;        // 0..7
    const int t = lane & 3;         // 0..3
    const int warp_m = warp >> 1;   // 0..3  (32 rows each)
    const int warp_n = warp & 1;    // 0..1  (64 cols each)

    float acc[2][8][4] = {};

    const int KT = K / BK;

    auto load_stage = [&](int s, int kt) {
        const int k0 = kt * BK;
        #pragma unroll
        for (int i = 0; i < 4; i++) {
            int idx = i * 256 + tid;           // 1024 float4 of A tile
            int r = idx >> 3, c4 = (idx & 7) * 4;
            CP16(&As[s * ASZ + r * PA + c4], &A[(size_t)(m0 + r) * K + k0 + c4]);
        }
        #pragma unroll
        for (int i = 0; i < 4; i++) {
            int idx = i * 256 + tid;           // 1024 float4 of B tile
            int r = idx >> 5, c4 = (idx & 31) * 4;
            CP16(&Bs[s * BSZ + r * PB + c4], &Bm[(size_t)(k0 + r) * N + n0 + c4]);
        }
    };

    load_stage(0, 0);
    CP_COMMIT();

    for (int kt = 0; kt < KT; kt++) {
        if (kt + 1 < KT) {
            load_stage((kt + 1) & 1, kt + 1);
            CP_COMMIT();
            CP_WAIT1();
        } else {
            CP_WAIT0();
        }
        __syncthreads();

        const float* as = &As[(kt & 1) * ASZ];
        const float* bs = &Bs[(kt & 1) * BSZ];

        #pragma unroll
        for (int ks = 0; ks < 2; ks++) {       // two k16 slabs per BK=32
            const int ko = ks * 16;
            uint32_t afh[2][4], afl[2][4];
            #pragma unroll
            for (int mt = 0; mt < 2; mt++) {
                int r = warp_m * 32 + mt * 16;
                float2 p0 = *(const float2*)&as[(r + g) * PA + ko + 2 * t];
                float2 p1 = *(const float2*)&as[(r + 8 + g) * PA + ko + 2 * t];
                float2 p2 = *(const float2*)&as[(r + g) * PA + ko + 2 * t + 8];
                float2 p3 = *(const float2*)&as[(r + 8 + g) * PA + ko + 2 * t + 8];
                bsplit2(p0.x, p0.y, afh[mt][0], afl[mt][0]);
                bsplit2(p1.x, p1.y, afh[mt][1], afl[mt][1]);
                bsplit2(p2.x, p2.y, afh[mt][2], afl[mt][2]);
                bsplit2(p3.x, p3.y, afh[mt][3], afl[mt][3]);
            }
            #pragma unroll
            for (int nt = 0; nt < 8; nt++) {
                int cb = warp_n * 64 + nt * 8 + g;
                uint32_t bh0, bl0, bh1, bl1;
                bsplit2(bs[(ko + 2 * t) * PB + cb],     bs[(ko + 2 * t + 1) * PB + cb], bh0, bl0);
                bsplit2(bs[(ko + 2 * t + 8) * PB + cb], bs[(ko + 2 * t + 9) * PB + cb], bh1, bl1);
                mma3(acc[0][nt], afh[0], afl[0], bh0, bh1, bl0, bl1);
                mma3(acc[1][nt], afh[1], afl[1], bh0, bh1, bl0, bl1);
            }
        }
        __syncthreads();
    }

    // epilogue: + bias, fp32 out
    #pragma unroll
    for (int mt = 0; mt < 2; mt++) {
        int r0 = m0 + warp_m * 32 + mt * 16 + g;
        #pragma unroll
        for (int nt = 0; nt < 8; nt++) {
            int c = n0 + warp_n * 64 + nt * 8 + 2 * t;
            float bz0 = bias[c], bz1 = bias[c + 1];
            float2 v0 = make_float2(acc[mt][nt][0] + bz0, acc[mt][nt][1] + bz1);
            float2 v1 = make_float2(acc[mt][nt][2] + bz0, acc[mt][nt][3] + bz1);
            *(float2*)&Cm[(size_t)r0 * N + c] = v0;
            *(float2*)&Cm[(size_t)(r0 + 8) * N + c] = v1;
        }
    }
}

// ---------------------------------------------------------------------------
// Flash attention (no sqrt(d) scaling). bf16x3 mma.
// Grid: (B*H, N/128). 256 threads = 8 warps, warp owns 16 query rows.
// Q,K,P pre-split into packed bf16x2 hi/lo smem (u32 words, pitch 36 words).
// V kept fp32 (pitch 68), split on read.
// ---------------------------------------------------------------------------
constexpr int PW = 36;                 // u32-word pitch for Qh/Ql/Kh/Kl/Ph/Pl
constexpr int PV = 68;                 // fp32 pitch for V: 2*68 mod 32 == 8 -> (8t+g) CF
constexpr int QW = 128 * PW;           // u32 words
constexpr int KW = 64 * PW;
constexpr int PWsz = 128 * PW;
constexpr int VSZ = 64 * PV;           // floats
constexpr size_t FL_SMEM = (size_t)(2 * QW + 2 * KW + 2 * PWsz + VSZ) * 4;

__global__ __launch_bounds__(256) void flash_attn(
    const float* __restrict__ qkv, float* __restrict__ attn_out)
{
    extern __shared__ uint32_t smw[];
    uint32_t* Qh = smw;
    uint32_t* Ql = Qh + QW;
    uint32_t* Kh = Ql + QW;
    uint32_t* Kl = Kh + KW;
    uint32_t* Ph = Kl + KW;
    uint32_t* Pl = Ph + PWsz;
    float*    Vs = (float*)(Pl + PWsz);

    const int tid = threadIdx.x;
    const int bh = blockIdx.x;
    const int b = bh / Hh, h = bh % Hh;
    const int q0 = blockIdx.y * 128;

    const int warp = tid >> 5;
    const int lane = tid & 31;
    const int g = lane >> 2;
    const int t = lane & 3;

    const size_t row_stride = (size_t)3 * Cc;
    const size_t base = (size_t)(b * Nn) * row_stride;
    const int qoff = h * Dd;
    const int koff = Cc + h * Dd;
    const int voff = 2 * Cc + h * Dd;

    // load + split Q tile (128 x 64) once: 4096 float2
    #pragma unroll
    for (int i = 0; i < 16; i++) {
        int idx = i * 256 + tid;
        int r = idx >> 5, w = idx & 31;
        float2 v = *(const float2*)&qkv[base + (size_t)(q0 + r) * row_stride + qoff + 2 * w];
        bsplit2(v.x, v.y, Qh[r * PW + w], Ql[r * PW + w]);
    }

    float m_run[2] = { -1e30f, -1e30f };
    float l_run[2] = { 0.f, 0.f };
    float oacc[8][4] = {};

    const int rq = warp * 16;

    for (int kt = 0; kt < Nn / 64; kt++) {
        const int k0 = kt * 64;
        __syncthreads();   // previous iter's K/V reads done; Q ready (iter 0)

        // load + split K (64x64 -> 2048 float2), load V fp32 (64x64 -> 1024 float4)
        #pragma unroll
        for (int i = 0; i < 8; i++) {
            int idx = i * 256 + tid;
            int r = idx >> 5, w = idx & 31;
            float2 kv = *(const float2*)&qkv[base + (size_t)(k0 + r) * row_stride + koff + 2 * w];
            bsplit2(kv.x, kv.y, Kh[r * PW + w], Kl[r * PW + w]);
        }
        #pragma unroll
        for (int i = 0; i < 4; i++) {
            int idx = i * 256 + tid;
            int r = idx >> 4, c4 = (idx & 15) * 4;
            float4 vv = *(const float4*)&qkv[base + (size_t)(k0 + r) * row_stride + voff + c4];
            *(float4*)&Vs[r * PV + c4] = vv;
        }
        __syncthreads();

        // S = Q K^T  (16 x 64 per warp), bf16x3; k = d (4 slabs of 16)
        float s[8][4] = {};
        #pragma unroll
        for (int ks = 0; ks < 4; ks++) {
            uint32_t ah[4], al[4];
            int w0 = 8 * ks + t;
            ah[0] = Qh[(rq + g) * PW + w0];     al[0] = Ql[(rq + g) * PW + w0];
            ah[1] = Qh[(rq + 8 + g) * PW + w0]; al[1] = Ql[(rq + 8 + g) * PW + w0];
            ah[2] = Qh[(rq + g) * PW + w0 + 4];     al[2] = Ql[(rq + g) * PW + w0 + 4];
            ah[3] = Qh[(rq + 8 + g) * PW + w0 + 4]; al[3] = Ql[(rq + 8 + g) * PW + w0 + 4];
            #pragma unroll
            for (int nt = 0; nt < 8; nt++) {
                int kr = (nt * 8 + g) * PW;
                uint32_t bh0 = Kh[kr + w0], bh1 = Kh[kr + w0 + 4];
                uint32_t bl0 = Kl[kr + w0], bl1 = Kl[kr + w0 + 4];
                mma3(s[nt], ah, al, bh0, bh1, bl0, bl1);
            }
        }

        // online softmax per row (2 rows per thread: g, g+8)
        #pragma unroll
        for (int rr = 0; rr < 2; rr++) {
            int j0 = rr * 2;
            float mx = -1e30f;
            #pragma unroll
            for (int nt = 0; nt < 8; nt++)
                mx = fmaxf(mx, fmaxf(s[nt][j0], s[nt][j0 + 1]));
            mx = fmaxf(mx, __shfl_xor_sync(0xffffffffu, mx, 1));
            mx = fmaxf(mx, __shfl_xor_sync(0xffffffffu, mx, 2));
            float newm = fmaxf(m_run[rr], mx);
            float scale = __expf(m_run[rr] - newm);
            m_run[rr] = newm;
            float rsum = 0.f;
            #pragma unroll
            for (int nt = 0; nt < 8; nt++) {
                float p0 = __expf(s[nt][j0] - newm);
                float p1 = __expf(s[nt][j0 + 1] - newm);
                s[nt][j0] = p0; s[nt][j0 + 1] = p1;
                rsum += p0 + p1;
            }
            rsum += __shfl_xor_sync(0xffffffffu, rsum, 1);
            rsum += __shfl_xor_sync(0xffffffffu, rsum, 2);
            l_run[rr] = l_run[rr] * scale + rsum;
            #pragma unroll
            for (int nt = 0; nt < 8; nt++) {
                oacc[nt][j0] *= scale;
                oacc[nt][j0 + 1] *= scale;
            }
        }

        // P -> smem split bf16 hi/lo (per-warp private rows)
        #pragma unroll
        for (int nt = 0; nt < 8; nt++) {
            int w = nt * 4 + t;
            bsplit2(s[nt][0], s[nt][1], Ph[(rq + g) * PW + w],     Pl[(rq + g) * PW + w]);
            bsplit2(s[nt][2], s[nt][3], Ph[(rq + 8 + g) * PW + w], Pl[(rq + 8 + g) * PW + w]);
        }
        __syncwarp();

        // O += P V   (k = key 64, 4 slabs), bf16x3; V split on read
        #pragma unroll
        for (int ks = 0; ks < 4; ks++) {
            uint32_t ah[4], al[4];
            int w0 = 8 * ks + t;
            ah[0] = Ph[(rq + g) * PW + w0];     al[0] = Pl[(rq + g) * PW + w0];
            ah[1] = Ph[(rq + 8 + g) * PW + w0]; al[1] = Pl[(rq + 8 + g) * PW + w0];
            ah[2] = Ph[(rq + g) * PW + w0 + 4];     al[2] = Pl[(rq + g) * PW + w0 + 4];
            ah[3] = Ph[(rq + 8 + g) * PW + w0 + 4]; al[3] = Pl[(rq + 8 + g) * PW + w0 + 4];
            int kb = 16 * ks + 2 * t;
            #pragma unroll
            for (int nt = 0; nt < 8; nt++) {
                int col = nt * 8 + g;
                uint32_t bh0, bl0, bh1, bl1;
                bsplit2(Vs[kb * PV + col],       Vs[(kb + 1) * PV + col], bh0, bl0);
                bsplit2(Vs[(kb + 8) * PV + col], Vs[(kb + 9) * PV + col], bh1, bl1);
                mma3(oacc[nt], ah, al, bh0, bh1, bl0, bl1);
            }
        }
    }

    // normalize + write out: attn_out[(b*N + n) * C + h*D + d]
    float inv0 = 1.f / l_run[0];
    float inv1 = 1.f / l_run[1];
    size_t orow0 = (size_t)(b * Nn + q0 + rq + g) * Cc + h * Dd;
    size_t orow1 = (size_t)(b * Nn + q0 + rq + 8 + g) * Cc + h * Dd;
    #pragma unroll
    for (int nt = 0; nt < 8; nt++) {
        int c = nt * 8 + 2 * t;
        *(float2*)&attn_out[orow0 + c] = make_float2(oacc[nt][0] * inv0, oacc[nt][1] * inv0);
        *(float2*)&attn_out[orow1 + c] = make_float2(oacc[nt][2] * inv1, oacc[nt][3] * inv1);
    }
}

// ---------------------------------------------------------------------------
// launch
// ---------------------------------------------------------------------------
extern "C" void kernel_launch(void* const* d_in, const int* in_sizes, int n_in,
                              void* d_out, int out_size)
{
    const float* x     = (const float*)d_in[0];
    const float* w_in  = (const float*)d_in[1];
    const float* b_in  = (const float*)d_in[2];
    const float* w_out = (const float*)d_in[3];
    const float* b_out = (const float*)d_in[4];
    float* out = (float*)d_out;

    float* qkv;
    float* attn;
    cudaGetSymbolAddress((void**)&qkv, g_qkv);
    cudaGetSymbolAddress((void**)&attn, g_attn);

    cudaFuncSetAttribute(gemm_bias_bf16x3, cudaFuncAttributeMaxDynamicSharedMemorySize,
                         (int)GEMM_SMEM);
    cudaFuncSetAttribute(flash_attn, cudaFuncAttributeMaxDynamicSharedMemorySize,
                         (int)FL_SMEM);

    const int M = Bb * Nn;  // 8192

    // 1) qkv = x @ w_in + b_in     (8192 x 3072 x 1024)
    gemm_bias_bf16x3<<<dim3(3 * Cc / BN, M / BM), 256, GEMM_SMEM>>>(
        x, w_in, b_in, qkv, M, 3 * Cc, Cc);

    // 2) flash attention -> attn (B,N,C)
    flash_attn<<<dim3(Bb * Hh, Nn / 128), 256, FL_SMEM>>>(qkv, attn);

    // 3) out = attn @ w_out + b_out   (8192 x 1024 x 1024)
    gemm_bias_bf16x3<<<dim3(Cc / BN, M / BM), 256, GEMM_SMEM>>>(
        attn, w_out, b_out, out, M, Cc, Cc);
}

// round 4
// speedup vs baseline: 1.6525x; 1.0377x over previous
#include <cuda_runtime.h>
#include <cuda_bf16.h>
#include <cstdint>
#include <cstddef>

#define Bb 4
#define Nn 2048
#define Cc 1024
#define Hh 16
#define Dd 64

// Scratch (allocation-free rule: __device__ globals)
__device__ float g_qkv[(size_t)Bb * Nn * 3 * Cc];   // (B,N,3C)
__device__ float g_attn[(size_t)Bb * Nn * Cc];      // (B,N,C)

// ---------------------------------------------------------------------------
// helpers
// ---------------------------------------------------------------------------
// bf16x3 split of a pair: h = packed bf16x2 (low half = x0), l = residuals.
__device__ __forceinline__ void bsplit2(float x0, float x1, uint32_t& h, uint32_t& l) {
    __nv_bfloat162 hv = __floats2bfloat162_rn(x0, x1);
    float2 hf = __bfloat1622float2(hv);
    __nv_bfloat162 lv = __floats2bfloat162_rn(x0 - hf.x, x1 - hf.y);
    h = *reinterpret_cast<uint32_t*>(&hv);
    l = *reinterpret_cast<uint32_t*>(&lv);
}

// m16n8k16 bf16 mma, fp32 accumulate
__device__ __forceinline__ void mmabf(float* c, const uint32_t* a, uint32_t b0, uint32_t b1) {
    asm volatile(
        "mma.sync.aligned.m16n8k16.row.col.f32.bf16.bf16.f32 "
        "{%0,%1,%2,%3},{%4,%5,%6,%7},{%8,%9},{%0,%1,%2,%3};"
        : "+f"(c[0]), "+f"(c[1]), "+f"(c[2]), "+f"(c[3])
        : "r"(a[0]), "r"(a[1]), "r"(a[2]), "r"(a[3]), "r"(b0), "r"(b1));
}

// error-compensated: c += al*bh + ah*bl + ah*bh
__device__ __forceinline__ void mma3(float* c,
                                     const uint32_t* ah, const uint32_t* al,
                                     uint32_t bh0, uint32_t bh1,
                                     uint32_t bl0, uint32_t bl1) {
    mmabf(c, al, bh0, bh1);
    mmabf(c, ah, bl0, bl1);
    mmabf(c, ah, bh0, bh1);
}

// ---------------------------------------------------------------------------
// GEMM: C[M,N] = A[M,K] @ B[K,N] + bias[N]  (row-major fp32, bf16x3)
// Block 128x128, K-tile 32, 256 threads, 8 warps (4 warp_m x 2 warp_n).
// A stored as hi/lo packed-bf16x2 words along K: Ah[r][w] = pack(A[r][2w],A[r][2w+1])
// B stored k-pair-packed: Bh[k2][n] = pack(B[2k2][n], B[2k2+1][n])
// ---------------------------------------------------------------------------
constexpr int BM = 128, BN = 128, BK = 32;
constexpr int PAW = 20;                 // A word pitch (16 data words)
constexpr int PBW = 132;                // B word pitch (128 data words)
constexpr int AWSZ = BM * PAW;          // 2560 words
constexpr int BWSZ = (BK / 2) * PBW;    // 2112 words
constexpr size_t GEMM_SMEM = (size_t)(2 * AWSZ + 2 * BWSZ) * 2 * 4;  // dbl-buf

__global__ __launch_bounds__(256) void gemm_bias_bf16x3(
    const float* __restrict__ A, const float* __restrict__ Bm,
    const float* __restrict__ bias, float* __restrict__ Cm,
    int M, int N, int K)
{
    extern __shared__ uint32_t smw[];
    uint32_t* Ah = smw;                 // [2][AWSZ]
    uint32_t* Al = Ah + 2 * AWSZ;
    uint32_t* Bh = Al + 2 * AWSZ;       // [2][BWSZ]
    uint32_t* Bl = Bh + 2 * BWSZ;

    const int tid = threadIdx.x;
    const int m0 = blockIdx.y * BM;
    const int n0 = blockIdx.x * BN;

    const int warp = tid >> 5;
    const int lane = tid & 31;
    const int g = lane >> 2;        // 0..7
    const int t = lane & 3;         // 0..3
    const int warp_m = warp >> 1;   // 0..3
    const int warp_n = warp & 1;    // 0..1

    float acc[2][8][4] = {};
    const int KT = K / BK;

    float2 a_reg[8];
    float2 b_reg[8];

    auto ldg_stage = [&](int kt) {
        const int k0 = kt * BK;
        #pragma unroll
        for (int i = 0; i < 8; i++) {
            int idx = i * 256 + tid;            // 2048 items: r x w
            int r = idx >> 4, w = idx & 15;
            a_reg[i] = *(const float2*)&A[(size_t)(m0 + r) * K + k0 + 2 * w];
        }
        #pragma unroll
        for (int i = 0; i < 4; i++) {
            int idx = i * 256 + tid;            // 1024 items: k2 x n2
            int k2 = idx >> 6, n2 = idx & 63;
            b_reg[2 * i]     = *(const float2*)&Bm[(size_t)(k0 + 2 * k2) * N + n0 + 2 * n2];
            b_reg[2 * i + 1] = *(const float2*)&Bm[(size_t)(k0 + 2 * k2 + 1) * N + n0 + 2 * n2];
        }
    };

    auto sts_stage = [&](int s) {
        uint32_t* ah = Ah + s * AWSZ;
        uint32_t* al = Al + s * AWSZ;
        uint32_t* bhp = Bh + s * BWSZ;
        uint32_t* blp = Bl + s * BWSZ;
        #pragma unroll
        for (int i = 0; i < 8; i++) {
            int idx = i * 256 + tid;
            int r = idx >> 4, w = idx & 15;
            bsplit2(a_reg[i].x, a_reg[i].y, ah[r * PAW + w], al[r * PAW + w]);
        }
        #pragma unroll
        for (int i = 0; i < 4; i++) {
            int idx = i * 256 + tid;
            int k2 = idx >> 6, n2 = idx & 63;
            uint32_t h0, l0, h1, l1;
            bsplit2(b_reg[2 * i].x, b_reg[2 * i + 1].x, h0, l0);  // col 2n2
            bsplit2(b_reg[2 * i].y, b_reg[2 * i + 1].y, h1, l1);  // col 2n2+1
            *(uint2*)&bhp[k2 * PBW + 2 * n2] = make_uint2(h0, h1);
            *(uint2*)&blp[k2 * PBW + 2 * n2] = make_uint2(l0, l1);
        }
    };

    ldg_stage(0);
    sts_stage(0);
    __syncthreads();

    for (int kt = 0; kt < KT; kt++) {
        if (kt + 1 < KT) ldg_stage(kt + 1);

        const uint32_t* ah = Ah + (kt & 1) * AWSZ;
        const uint32_t* al = Al + (kt & 1) * AWSZ;
        const uint32_t* bhp = Bh + (kt & 1) * BWSZ;
        const uint32_t* blp = Bl + (kt & 1) * BWSZ;

        #pragma unroll
        for (int ks = 0; ks < 2; ks++) {
            const int w0 = 8 * ks + t;
            uint32_t afh[2][4], afl[2][4];
            #pragma unroll
            for (int mt = 0; mt < 2; mt++) {
                int r = warp_m * 32 + mt * 16;
                afh[mt][0] = ah[(r + g) * PAW + w0];
                afh[mt][1] = ah[(r + 8 + g) * PAW + w0];
                afh[mt][2] = ah[(r + g) * PAW + w0 + 4];
                afh[mt][3] = ah[(r + 8 + g) * PAW + w0 + 4];
                afl[mt][0] = al[(r + g) * PAW + w0];
                afl[mt][1] = al[(r + 8 + g) * PAW + w0];
                afl[mt][2] = al[(r + g) * PAW + w0 + 4];
                afl[mt][3] = al[(r + 8 + g) * PAW + w0 + 4];
            }
            const int kr0 = (8 * ks + t) * PBW;
            const int kr1 = (8 * ks + t + 4) * PBW;
            #pragma unroll
            for (int nt = 0; nt < 8; nt++) {
                int cb = warp_n * 64 + nt * 8 + g;
                uint32_t bh0 = bhp[kr0 + cb], bh1 = bhp[kr1 + cb];
                uint32_t bl0 = blp[kr0 + cb], bl1 = blp[kr1 + cb];
                mma3(acc[0][nt], afh[0], afl[0], bh0, bh1, bl0, bl1);
                mma3(acc[1][nt], afh[1], afl[1], bh0, bh1, bl0, bl1);
            }
        }

        if (kt + 1 < KT) sts_stage((kt + 1) & 1);
        __syncthreads();
    }

    // epilogue: + bias, fp32 out
    #pragma unroll
    for (int mt = 0; mt < 2; mt++) {
        int r0 = m0 + warp_m * 32 + mt * 16 + g;
        #pragma unroll
        for (int nt = 0; nt < 8; nt++) {
            int c = n0 + warp_n * 64 + nt * 8 + 2 * t;
            float bz0 = bias[c], bz1 = bias[c + 1];
            float2 v0 = make_float2(acc[mt][nt][0] + bz0, acc[mt][nt][1] + bz1);
            float2 v1 = make_float2(acc[mt][nt][2] + bz0, acc[mt][nt][3] + bz1);
            *(float2*)&Cm[(size_t)r0 * N + c] = v0;
            *(float2*)&Cm[(size_t)(r0 + 8) * N + c] = v1;
        }
    }
}

// ---------------------------------------------------------------------------
// Flash attention (no sqrt(d) scaling). bf16x3 mma.
// Grid: (B*H, N/128). 256 threads = 8 warps, warp owns 16 query rows.
// Q,K,P: packed bf16x2 hi/lo words along d (pitch 36 words).
// V: k-pair-packed hi/lo words Vh[k2][n] = pack(V[2k2][n],V[2k2+1][n]), pitch 68.
// ---------------------------------------------------------------------------
constexpr int PW = 36;                 // word pitch for Qh/Ql/Kh/Kl/Ph/Pl
constexpr int PVW = 68;                // word pitch for Vh/Vl
constexpr int QW = 128 * PW;
constexpr int KW = 64 * PW;
constexpr int PWsz = 128 * PW;
constexpr int VWSZ = 32 * PVW;         // 32 k-pairs x 64(+pad) cols
constexpr size_t FL_SMEM = (size_t)(2 * QW + 2 * KW + 2 * PWsz + 2 * VWSZ) * 4;

__global__ __launch_bounds__(256) void flash_attn(
    const float* __restrict__ qkv, float* __restrict__ attn_out)
{
    extern __shared__ uint32_t smw[];
    uint32_t* Qh = smw;
    uint32_t* Ql = Qh + QW;
    uint32_t* Kh = Ql + QW;
    uint32_t* Kl = Kh + KW;
    uint32_t* Ph = Kl + KW;
    uint32_t* Pl = Ph + PWsz;
    uint32_t* Vh = Pl + PWsz;
    uint32_t* Vl = Vh + VWSZ;

    const int tid = threadIdx.x;
    const int bh = blockIdx.x;
    const int b = bh / Hh, h = bh % Hh;
    const int q0 = blockIdx.y * 128;

    const int warp = tid >> 5;
    const int lane = tid & 31;
    const int g = lane >> 2;
    const int t = lane & 3;

    const size_t row_stride = (size_t)3 * Cc;
    const size_t base = (size_t)(b * Nn) * row_stride;
    const int qoff = h * Dd;
    const int koff = Cc + h * Dd;
    const int voff = 2 * Cc + h * Dd;

    // load + split Q tile (128 x 64) once: 4096 float2
    #pragma unroll
    for (int i = 0; i < 16; i++) {
        int idx = i * 256 + tid;
        int r = idx >> 5, w = idx & 31;
        float2 v = *(const float2*)&qkv[base + (size_t)(q0 + r) * row_stride + qoff + 2 * w];
        bsplit2(v.x, v.y, Qh[r * PW + w], Ql[r * PW + w]);
    }

    float m_run[2] = { -1e30f, -1e30f };
    float l_run[2] = { 0.f, 0.f };
    float oacc[8][4] = {};

    const int rq = warp * 16;

    for (int kt = 0; kt < Nn / 64; kt++) {
        const int k0 = kt * 64;
        __syncthreads();   // previous iter's K/V reads done; Q ready (iter 0)

        // load + split K (64x64 -> 2048 float2)
        #pragma unroll
        for (int i = 0; i < 8; i++) {
            int idx = i * 256 + tid;
            int r = idx >> 5, w = idx & 31;
            float2 kv = *(const float2*)&qkv[base + (size_t)(k0 + r) * row_stride + koff + 2 * w];
            bsplit2(kv.x, kv.y, Kh[r * PW + w], Kl[r * PW + w]);
        }
        // load + split V k-pair-packed (64x64 -> 1024 items of 2 cols)
        #pragma unroll
        for (int i = 0; i < 4; i++) {
            int idx = i * 256 + tid;
            int k2 = idx >> 5, n2 = idx & 31;
            float2 v0 = *(const float2*)&qkv[base + (size_t)(k0 + 2 * k2) * row_stride + voff + 2 * n2];
            float2 v1 = *(const float2*)&qkv[base + (size_t)(k0 + 2 * k2 + 1) * row_stride + voff + 2 * n2];
            uint32_t h0, l0, h1, l1;
            bsplit2(v0.x, v1.x, h0, l0);
            bsplit2(v0.y, v1.y, h1, l1);
            *(uint2*)&Vh[k2 * PVW + 2 * n2] = make_uint2(h0, h1);
            *(uint2*)&Vl[k2 * PVW + 2 * n2] = make_uint2(l0, l1);
        }
        __syncthreads();

        // S = Q K^T  (16 x 64 per warp), bf16x3; k = d (4 slabs of 16)
        float s[8][4] = {};
        #pragma unroll
        for (int ks = 0; ks < 4; ks++) {
            uint32_t ah[4], al[4];
            int w0 = 8 * ks + t;
            ah[0] = Qh[(rq + g) * PW + w0];         al[0] = Ql[(rq + g) * PW + w0];
            ah[1] = Qh[(rq + 8 + g) * PW + w0];     al[1] = Ql[(rq + 8 + g) * PW + w0];
            ah[2] = Qh[(rq + g) * PW + w0 + 4];     al[2] = Ql[(rq + g) * PW + w0 + 4];
            ah[3] = Qh[(rq + 8 + g) * PW + w0 + 4]; al[3] = Ql[(rq + 8 + g) * PW + w0 + 4];
            #pragma unroll
            for (int nt = 0; nt < 8; nt++) {
                int kr = (nt * 8 + g) * PW;
                uint32_t bh0 = Kh[kr + w0], bh1 = Kh[kr + w0 + 4];
                uint32_t bl0 = Kl[kr + w0], bl1 = Kl[kr + w0 + 4];
                mma3(s[nt], ah, al, bh0, bh1, bl0, bl1);
            }
        }

        // online softmax per row (2 rows per thread: g, g+8)
        #pragma unroll
        for (int rr = 0; rr < 2; rr++) {
            int j0 = rr * 2;
            float mx = -1e30f;
            #pragma unroll
            for (int nt = 0; nt < 8; nt++)
                mx = fmaxf(mx, fmaxf(s[nt][j0], s[nt][j0 + 1]));
            mx = fmaxf(mx, __shfl_xor_sync(0xffffffffu, mx, 1));
            mx = fmaxf(mx, __shfl_xor_sync(0xffffffffu, mx, 2));
            float newm = fmaxf(m_run[rr], mx);
            float scale = __expf(m_run[rr] - newm);
            m_run[rr] = newm;
            float rsum = 0.f;
            #pragma unroll
            for (int nt = 0; nt < 8; nt++) {
                float p0 = __expf(s[nt][j0] - newm);
                float p1 = __expf(s[nt][j0 + 1] - newm);
                s[nt][j0] = p0; s[nt][j0 + 1] = p1;
                rsum += p0 + p1;
            }
            rsum += __shfl_xor_sync(0xffffffffu, rsum, 1);
            rsum += __shfl_xor_sync(0xffffffffu, rsum, 2);
            l_run[rr] = l_run[rr] * scale + rsum;
            #pragma unroll
            for (int nt = 0; nt < 8; nt++) {
                oacc[nt][j0] *= scale;
                oacc[nt][j0 + 1] *= scale;
            }
        }

        // P -> smem split bf16 hi/lo (per-warp private rows)
        #pragma unroll
        for (int nt = 0; nt < 8; nt++) {
            int w = nt * 4 + t;
            bsplit2(s[nt][0], s[nt][1], Ph[(rq + g) * PW + w],     Pl[(rq + g) * PW + w]);
            bsplit2(s[nt][2], s[nt][3], Ph[(rq + 8 + g) * PW + w], Pl[(rq + 8 + g) * PW + w]);
        }
        __syncwarp();

        // O += P V   (k = key 64, 4 slabs), bf16x3; V pre-split
        #pragma unroll
        for (int ks = 0; ks < 4; ks++) {
            uint32_t ah[4], al[4];
            int w0 = 8 * ks + t;
            ah[0] = Ph[(rq + g) * PW + w0];         al[0] = Pl[(rq + g) * PW + w0];
            ah[1] = Ph[(rq + 8 + g) * PW + w0];     al[1] = Pl[(rq + 8 + g) * PW + w0];
            ah[2] = Ph[(rq + g) * PW + w0 + 4];     al[2] = Pl[(rq + g) * PW + w0 + 4];
            ah[3] = Ph[(rq + 8 + g) * PW + w0 + 4]; al[3] = Pl[(rq + 8 + g) * PW + w0 + 4];
            const int kr0 = (8 * ks + t) * PVW;
            const int kr1 = (8 * ks + t + 4) * PVW;
            #pragma unroll
            for (int nt = 0; nt < 8; nt++) {
                int col = nt * 8 + g;
                uint32_t bh0 = Vh[kr0 + col], bh1 = Vh[kr1 + col];
                uint32_t bl0 = Vl[kr0 + col], bl1 = Vl[kr1 + col];
                mma3(oacc[nt], ah, al, bh0, bh1, bl0, bl1);
            }
        }
    }

    // normalize + write out: attn_out[(b*N + n) * C + h*D + d]
    float inv0 = 1.f / l_run[0];
    float inv1 = 1.f / l_run[1];
    size_t orow0 = (size_t)(b * Nn + q0 + rq + g) * Cc + h * Dd;
    size_t orow1 = (size_t)(b * Nn + q0 + rq + 8 + g) * Cc + h * Dd;
    #pragma unroll
    for (int nt = 0; nt < 8; nt++) {
        int c = nt * 8 + 2 * t;
        *(float2*)&attn_out[orow0 + c] = make_float2(oacc[nt][0] * inv0, oacc[nt][1] * inv0);
        *(float2*)&attn_out[orow1 + c] = make_float2(oacc[nt][2] * inv1, oacc[nt][3] * inv1);
    }
}

// ---------------------------------------------------------------------------
// launch
// ---------------------------------------------------------------------------
extern "C" void kernel_launch(void* const* d_in, const int* in_sizes, int n_in,
                              void* d_out, int out_size)
{
    const float* x     = (const float*)d_in[0];
    const float* w_in  = (const float*)d_in[1];
    const float* b_in  = (const float*)d_in[2];
    const float* w_out = (const float*)d_in[3];
    const float* b_out = (const float*)d_in[4];
    float* out = (float*)d_out;

    float* qkv;
    float* attn;
    cudaGetSymbolAddress((void**)&qkv, g_qkv);
    cudaGetSymbolAddress((void**)&attn, g_attn);

    cudaFuncSetAttribute(gemm_bias_bf16x3, cudaFuncAttributeMaxDynamicSharedMemorySize,
                         (int)GEMM_SMEM);
    cudaFuncSetAttribute(flash_attn, cudaFuncAttributeMaxDynamicSharedMemorySize,
                         (int)FL_SMEM);

    const int M = Bb * Nn;  // 8192

    // 1) qkv = x @ w_in + b_in     (8192 x 3072 x 1024)
    gemm_bias_bf16x3<<<dim3(3 * Cc / BN, M / BM), 256, GEMM_SMEM>>>(
        x, w_in, b_in, qkv, M, 3 * Cc, Cc);

    // 2) flash attention -> attn (B,N,C)
    flash_attn<<<dim3(Bb * Hh, Nn / 128), 256, FL_SMEM>>>(qkv, attn);

    // 3) out = attn @ w_out + b_out   (8192 x 1024 x 1024)
    gemm_bias_bf16x3<<<dim3(Cc / BN, M / BM), 256, GEMM_SMEM>>>(
        attn, w_out, b_out, out, M, Cc, Cc);
}

// round 5
// speedup vs baseline: 1.9193x; 1.1615x over previous
#include <cuda_runtime.h>
#include <cuda_bf16.h>
#include <cstdint>
#include <cstddef>

#define Bb 4
#define Nn 2048
#define Cc 1024
#define Hh 16
#define Dd 64

// Scratch (allocation-free rule: __device__ globals)
__device__ float g_qkv[(size_t)Bb * Nn * 3 * Cc];   // (B,N,3C)
__device__ float g_attn[(size_t)Bb * Nn * Cc];      // (B,N,C)

// ---------------------------------------------------------------------------
// helpers
// ---------------------------------------------------------------------------
// bf16x3 split of a pair: h = packed bf16x2 (low half = x0), l = residuals.
__device__ __forceinline__ void bsplit2(float x0, float x1, uint32_t& h, uint32_t& l) {
    __nv_bfloat162 hv = __floats2bfloat162_rn(x0, x1);
    float2 hf = __bfloat1622float2(hv);
    __nv_bfloat162 lv = __floats2bfloat162_rn(x0 - hf.x, x1 - hf.y);
    h = *reinterpret_cast<uint32_t*>(&hv);
    l = *reinterpret_cast<uint32_t*>(&lv);
}

// m16n8k16 bf16 mma, fp32 accumulate
__device__ __forceinline__ void mmabf(float* c, const uint32_t* a, uint32_t b0, uint32_t b1) {
    asm volatile(
        "mma.sync.aligned.m16n8k16.row.col.f32.bf16.bf16.f32 "
        "{%0,%1,%2,%3},{%4,%5,%6,%7},{%8,%9},{%0,%1,%2,%3};"
        : "+f"(c[0]), "+f"(c[1]), "+f"(c[2]), "+f"(c[3])
        : "r"(a[0]), "r"(a[1]), "r"(a[2]), "r"(a[3]), "r"(b0), "r"(b1));
}

// error-compensated: c += al*bh + ah*bl + ah*bh
__device__ __forceinline__ void mma3(float* c,
                                     const uint32_t* ah, const uint32_t* al,
                                     uint32_t bh0, uint32_t bh1,
                                     uint32_t bl0, uint32_t bl1) {
    mmabf(c, al, bh0, bh1);
    mmabf(c, ah, bl0, bl1);
    mmabf(c, ah, bh0, bh1);
}

// ---------------------------------------------------------------------------
// GEMM: C[M,N] = A[M,K] @ B[K,N] + bias[N]  (row-major fp32, bf16x3)
// Block 128x128, K-tile 32, 256 threads, 8 warps (4 warp_m x 2 warp_n).
// 2 CTAs/SM. A: hi/lo packed-bf16x2 words along K (pitch 20 words).
// B: k-pair-packed, pitch 136 words (conflict-free (8t+g) frag reads).
// ---------------------------------------------------------------------------
constexpr int BM = 128, BN = 128, BK = 32;
constexpr int PAW = 20;                 // A word pitch (16 data words)
constexpr int PBW = 136;                // B word pitch (128 data words)
constexpr int AWSZ = BM * PAW;          // 2560 words
constexpr int BWSZ = (BK / 2) * PBW;    // 2176 words
constexpr size_t GEMM_SMEM = (size_t)(2 * AWSZ + 2 * BWSZ) * 2 * 4;  // dbl-buf

__global__ __launch_bounds__(256, 2) void gemm_bias_bf16x3(
    const float* __restrict__ A, const float* __restrict__ Bm,
    const float* __restrict__ bias, float* __restrict__ Cm,
    int M, int N, int K)
{
    extern __shared__ uint32_t smw[];
    uint32_t* Ah = smw;                 // [2][AWSZ]
    uint32_t* Al = Ah + 2 * AWSZ;
    uint32_t* Bh = Al + 2 * AWSZ;       // [2][BWSZ]
    uint32_t* Bl = Bh + 2 * BWSZ;

    const int tid = threadIdx.x;
    const int m0 = blockIdx.y * BM;
    const int n0 = blockIdx.x * BN;

    const int warp = tid >> 5;
    const int lane = tid & 31;
    const int g = lane >> 2;        // 0..7
    const int t = lane & 3;         // 0..3
    const int warp_m = warp >> 1;   // 0..3
    const int warp_n = warp & 1;    // 0..1

    float acc[2][8][4] = {};
    const int KT = K / BK;

    float2 a_reg[8];
    float2 b_reg[8];

    auto ldg_stage = [&](int kt) {
        const int k0 = kt * BK;
        #pragma unroll
        for (int i = 0; i < 8; i++) {
            int idx = i * 256 + tid;            // 2048 items: r x w
            int r = idx >> 4, w = idx & 15;
            a_reg[i] = *(const float2*)&A[(size_t)(m0 + r) * K + k0 + 2 * w];
        }
        #pragma unroll
        for (int i = 0; i < 4; i++) {
            int idx = i * 256 + tid;            // 1024 items: k2 x n2
            int k2 = idx >> 6, n2 = idx & 63;
            b_reg[2 * i]     = *(const float2*)&Bm[(size_t)(k0 + 2 * k2) * N + n0 + 2 * n2];
            b_reg[2 * i + 1] = *(const float2*)&Bm[(size_t)(k0 + 2 * k2 + 1) * N + n0 + 2 * n2];
        }
    };

    auto sts_stage = [&](int s) {
        uint32_t* ah = Ah + s * AWSZ;
        uint32_t* al = Al + s * AWSZ;
        uint32_t* bhp = Bh + s * BWSZ;
        uint32_t* blp = Bl + s * BWSZ;
        #pragma unroll
        for (int i = 0; i < 8; i++) {
            int idx = i * 256 + tid;
            int r = idx >> 4, w = idx & 15;
            bsplit2(a_reg[i].x, a_reg[i].y, ah[r * PAW + w], al[r * PAW + w]);
        }
        #pragma unroll
        for (int i = 0; i < 4; i++) {
            int idx = i * 256 + tid;
            int k2 = idx >> 6, n2 = idx & 63;
            uint32_t h0, l0, h1, l1;
            bsplit2(b_reg[2 * i].x, b_reg[2 * i + 1].x, h0, l0);  // col 2n2
            bsplit2(b_reg[2 * i].y, b_reg[2 * i + 1].y, h1, l1);  // col 2n2+1
            *(uint2*)&bhp[k2 * PBW + 2 * n2] = make_uint2(h0, h1);
            *(uint2*)&blp[k2 * PBW + 2 * n2] = make_uint2(l0, l1);
        }
    };

    auto compute_slab = [&](const uint32_t* ah, const uint32_t* al,
                            const uint32_t* bhp, const uint32_t* blp, int ks) {
        const int w0 = 8 * ks + t;
        uint32_t afh[2][4], afl[2][4];
        #pragma unroll
        for (int mt = 0; mt < 2; mt++) {
            int r = warp_m * 32 + mt * 16;
            afh[mt][0] = ah[(r + g) * PAW + w0];
            afh[mt][1] = ah[(r + 8 + g) * PAW + w0];
            afh[mt][2] = ah[(r + g) * PAW + w0 + 4];
            afh[mt][3] = ah[(r + 8 + g) * PAW + w0 + 4];
            afl[mt][0] = al[(r + g) * PAW + w0];
            afl[mt][1] = al[(r + 8 + g) * PAW + w0];
            afl[mt][2] = al[(r + g) * PAW + w0 + 4];
            afl[mt][3] = al[(r + 8 + g) * PAW + w0 + 4];
        }
        const int kr0 = (8 * ks + t) * PBW;
        const int kr1 = (8 * ks + t + 4) * PBW;
        #pragma unroll
        for (int nt = 0; nt < 8; nt++) {
            int cb = warp_n * 64 + nt * 8 + g;
            uint32_t bh0 = bhp[kr0 + cb], bh1 = bhp[kr1 + cb];
            uint32_t bl0 = blp[kr0 + cb], bl1 = blp[kr1 + cb];
            mma3(acc[0][nt], afh[0], afl[0], bh0, bh1, bl0, bl1);
            mma3(acc[1][nt], afh[1], afl[1], bh0, bh1, bl0, bl1);
        }
    };

    ldg_stage(0);
    sts_stage(0);
    __syncthreads();

    for (int kt = 0; kt < KT; kt++) {
        const int s = kt & 1;
        const uint32_t* ah = Ah + s * AWSZ;
        const uint32_t* al = Al + s * AWSZ;
        const uint32_t* bhp = Bh + s * BWSZ;
        const uint32_t* blp = Bl + s * BWSZ;

        if (kt + 1 < KT) ldg_stage(kt + 1);
        compute_slab(ah, al, bhp, blp, 0);        // covers LDG latency
        if (kt + 1 < KT) sts_stage(s ^ 1);        // frees staging regs
        compute_slab(ah, al, bhp, blp, 1);
        __syncthreads();
    }

    // epilogue: + bias, fp32 out
    #pragma unroll
    for (int mt = 0; mt < 2; mt++) {
        int r0 = m0 + warp_m * 32 + mt * 16 + g;
        #pragma unroll
        for (int nt = 0; nt < 8; nt++) {
            int c = n0 + warp_n * 64 + nt * 8 + 2 * t;
            float bz0 = bias[c], bz1 = bias[c + 1];
            float2 v0 = make_float2(acc[mt][nt][0] + bz0, acc[mt][nt][1] + bz1);
            float2 v1 = make_float2(acc[mt][nt][2] + bz0, acc[mt][nt][3] + bz1);
            *(float2*)&Cm[(size_t)r0 * N + c] = v0;
            *(float2*)&Cm[(size_t)(r0 + 8) * N + c] = v1;
        }
    }
}

// ---------------------------------------------------------------------------
// Flash attention (no sqrt(d) scaling). bf16x3 mma. 2 CTAs/SM.
// Grid: (B*H, N/128). 256 threads = 8 warps, warp owns 16 query rows.
// Q,K: packed bf16x2 hi/lo words along d (pitch 36 words).
// V: k-pair-packed hi/lo words, pitch 72 (conflict-free frag reads).
// P never touches smem: S C-fragment == PV A-fragment layout identity.
// ---------------------------------------------------------------------------
constexpr int PW = 36;                 // word pitch for Qh/Ql/Kh/Kl
constexpr int PVW = 72;                // word pitch for Vh/Vl
constexpr int QW = 128 * PW;
constexpr int KW = 64 * PW;
constexpr int VWSZ = 32 * PVW;         // 32 k-pairs x 64(+pad) cols
constexpr size_t FL_SMEM = (size_t)(2 * QW + 2 * KW + 2 * VWSZ) * 4;

__global__ __launch_bounds__(256, 2) void flash_attn(
    const float* __restrict__ qkv, float* __restrict__ attn_out)
{
    extern __shared__ uint32_t smw[];
    uint32_t* Qh = smw;
    uint32_t* Ql = Qh + QW;
    uint32_t* Kh = Ql + QW;
    uint32_t* Kl = Kh + KW;
    uint32_t* Vh = Kl + KW;
    uint32_t* Vl = Vh + VWSZ;

    const int tid = threadIdx.x;
    const int bh = blockIdx.x;
    const int b = bh / Hh, h = bh % Hh;
    const int q0 = blockIdx.y * 128;

    const int warp = tid >> 5;
    const int lane = tid & 31;
    const int g = lane >> 2;
    const int t = lane & 3;

    const size_t row_stride = (size_t)3 * Cc;
    const size_t base = (size_t)(b * Nn) * row_stride;
    const int qoff = h * Dd;
    const int koff = Cc + h * Dd;
    const int voff = 2 * Cc + h * Dd;

    // load + split Q tile (128 x 64) once: 4096 float2
    #pragma unroll
    for (int i = 0; i < 16; i++) {
        int idx = i * 256 + tid;
        int r = idx >> 5, w = idx & 31;
        float2 v = *(const float2*)&qkv[base + (size_t)(q0 + r) * row_stride + qoff + 2 * w];
        bsplit2(v.x, v.y, Qh[r * PW + w], Ql[r * PW + w]);
    }

    float m_run[2] = { -1e30f, -1e30f };
    float l_run[2] = { 0.f, 0.f };
    float oacc[8][4] = {};

    const int rq = warp * 16;

    for (int kt = 0; kt < Nn / 64; kt++) {
        const int k0 = kt * 64;
        __syncthreads();   // previous iter's K/V reads done; Q ready (iter 0)

        // load + split K (64x64 -> 2048 float2)
        #pragma unroll
        for (int i = 0; i < 8; i++) {
            int idx = i * 256 + tid;
            int r = idx >> 5, w = idx & 31;
            float2 kv = *(const float2*)&qkv[base + (size_t)(k0 + r) * row_stride + koff + 2 * w];
            bsplit2(kv.x, kv.y, Kh[r * PW + w], Kl[r * PW + w]);
        }
        // load + split V k-pair-packed (64x64 -> 1024 items of 2 cols)
        #pragma unroll
        for (int i = 0; i < 4; i++) {
            int idx = i * 256 + tid;
            int k2 = idx >> 5, n2 = idx & 31;
            float2 v0 = *(const float2*)&qkv[base + (size_t)(k0 + 2 * k2) * row_stride + voff + 2 * n2];
            float2 v1 = *(const float2*)&qkv[base + (size_t)(k0 + 2 * k2 + 1) * row_stride + voff + 2 * n2];
            uint32_t h0, l0, h1, l1;
            bsplit2(v0.x, v1.x, h0, l0);
            bsplit2(v0.y, v1.y, h1, l1);
            *(uint2*)&Vh[k2 * PVW + 2 * n2] = make_uint2(h0, h1);
            *(uint2*)&Vl[k2 * PVW + 2 * n2] = make_uint2(l0, l1);
        }
        __syncthreads();

        // S = Q K^T  (16 x 64 per warp), bf16x3; k = d (4 slabs of 16)
        float s[8][4] = {};
        #pragma unroll
        for (int ks = 0; ks < 4; ks++) {
            uint32_t ah[4], al[4];
            int w0 = 8 * ks + t;
            ah[0] = Qh[(rq + g) * PW + w0];         al[0] = Ql[(rq + g) * PW + w0];
            ah[1] = Qh[(rq + 8 + g) * PW + w0];     al[1] = Ql[(rq + 8 + g) * PW + w0];
            ah[2] = Qh[(rq + g) * PW + w0 + 4];     al[2] = Ql[(rq + g) * PW + w0 + 4];
            ah[3] = Qh[(rq + 8 + g) * PW + w0 + 4]; al[3] = Ql[(rq + 8 + g) * PW + w0 + 4];
            #pragma unroll
            for (int nt = 0; nt < 8; nt++) {
                int kr = (nt * 8 + g) * PW;
                uint32_t bh0 = Kh[kr + w0], bh1 = Kh[kr + w0 + 4];
                uint32_t bl0 = Kl[kr + w0], bl1 = Kl[kr + w0 + 4];
                mma3(s[nt], ah, al, bh0, bh1, bl0, bl1);
            }
        }

        // online softmax per row (2 rows per thread: g, g+8)
        #pragma unroll
        for (int rr = 0; rr < 2; rr++) {
            int j0 = rr * 2;
            float mx = -1e30f;
            #pragma unroll
            for (int nt = 0; nt < 8; nt++)
                mx = fmaxf(mx, fmaxf(s[nt][j0], s[nt][j0 + 1]));
            mx = fmaxf(mx, __shfl_xor_sync(0xffffffffu, mx, 1));
            mx = fmaxf(mx, __shfl_xor_sync(0xffffffffu, mx, 2));
            float newm = fmaxf(m_run[rr], mx);
            float scale = __expf(m_run[rr] - newm);
            m_run[rr] = newm;
            float rsum = 0.f;
            #pragma unroll
            for (int nt = 0; nt < 8; nt++) {
                float p0 = __expf(s[nt][j0] - newm);
                float p1 = __expf(s[nt][j0 + 1] - newm);
                s[nt][j0] = p0; s[nt][j0 + 1] = p1;
                rsum += p0 + p1;
            }
            rsum += __shfl_xor_sync(0xffffffffu, rsum, 1);
            rsum += __shfl_xor_sync(0xffffffffu, rsum, 2);
            l_run[rr] = l_run[rr] * scale + rsum;
            #pragma unroll
            for (int nt = 0; nt < 8; nt++) {
                oacc[nt][j0] *= scale;
                oacc[nt][j0 + 1] *= scale;
            }
        }

        // O += P V  (k = key 64, 4 slabs), bf16x3.
        // P a-frags come straight from the S C-frags (layout identity):
        //   a word (row g,   k-pair 8ks+t)   = pack(s[2ks][0],  s[2ks][1])
        //   a word (row g+8, k-pair 8ks+t)   = pack(s[2ks][2],  s[2ks][3])
        //   a word (row g,   k-pair 8ks+4+t) = pack(s[2ks+1][0],s[2ks+1][1])
        //   a word (row g+8, k-pair 8ks+4+t) = pack(s[2ks+1][2],s[2ks+1][3])
        #pragma unroll
        for (int ks = 0; ks < 4; ks++) {
            uint32_t ah[4], al[4];
            bsplit2(s[2 * ks][0],     s[2 * ks][1],     ah[0], al[0]);
            bsplit2(s[2 * ks][2],     s[2 * ks][3],     ah[1], al[1]);
            bsplit2(s[2 * ks + 1][0], s[2 * ks + 1][1], ah[2], al[2]);
            bsplit2(s[2 * ks + 1][2], s[2 * ks + 1][3], ah[3], al[3]);
            const int kr0 = (8 * ks + t) * PVW;
            const int kr1 = (8 * ks + t + 4) * PVW;
            #pragma unroll
            for (int nt = 0; nt < 8; nt++) {
                int col = nt * 8 + g;
                uint32_t bh0 = Vh[kr0 + col], bh1 = Vh[kr1 + col];
                uint32_t bl0 = Vl[kr0 + col], bl1 = Vl[kr1 + col];
                mma3(oacc[nt], ah, al, bh0, bh1, bl0, bl1);
            }
        }
    }

    // normalize + write out: attn_out[(b*N + n) * C + h*D + d]
    float inv0 = 1.f / l_run[0];
    float inv1 = 1.f / l_run[1];
    size_t orow0 = (size_t)(b * Nn + q0 + rq + g) * Cc + h * Dd;
    size_t orow1 = (size_t)(b * Nn + q0 + rq + 8 + g) * Cc + h * Dd;
    #pragma unroll
    for (int nt = 0; nt < 8; nt++) {
        int c = nt * 8 + 2 * t;
        *(float2*)&attn_out[orow0 + c] = make_float2(oacc[nt][0] * inv0, oacc[nt][1] * inv0);
        *(float2*)&attn_out[orow1 + c] = make_float2(oacc[nt][2] * inv1, oacc[nt][3] * inv1);
    }
}

// ---------------------------------------------------------------------------
// launch
// ---------------------------------------------------------------------------
extern "C" void kernel_launch(void* const* d_in, const int* in_sizes, int n_in,
                              void* d_out, int out_size)
{
    const float* x     = (const float*)d_in[0];
    const float* w_in  = (const float*)d_in[1];
    const float* b_in  = (const float*)d_in[2];
    const float* w_out = (const float*)d_in[3];
    const float* b_out = (const float*)d_in[4];
    float* out = (float*)d_out;

    float* qkv;
    float* attn;
    cudaGetSymbolAddress((void**)&qkv, g_qkv);
    cudaGetSymbolAddress((void**)&attn, g_attn);

    cudaFuncSetAttribute(gemm_bias_bf16x3, cudaFuncAttributeMaxDynamicSharedMemorySize,
                         (int)GEMM_SMEM);
    cudaFuncSetAttribute(flash_attn, cudaFuncAttributeMaxDynamicSharedMemorySize,
                         (int)FL_SMEM);

    const int M = Bb * Nn;  // 8192

    // 1) qkv = x @ w_in + b_in     (8192 x 3072 x 1024)
    gemm_bias_bf16x3<<<dim3(3 * Cc / BN, M / BM), 256, GEMM_SMEM>>>(
        x, w_in, b_in, qkv, M, 3 * Cc, Cc);

    // 2) flash attention -> attn (B,N,C)
    flash_attn<<<dim3(Bb * Hh, Nn / 128), 256, FL_SMEM>>>(qkv, attn);

    // 3) out = attn @ w_out + b_out   (8192 x 1024 x 1024)
    gemm_bias_bf16x3<<<dim3(Cc / BN, M / BM), 256, GEMM_SMEM>>>(
        attn, w_out, b_out, out, M, Cc, Cc);
}